// round 12
// baseline (speedup 1.0000x reference)
#include <cuda_runtime.h>
#include <cuda_bf16.h>
#include <cuda_fp16.h>
#include <math.h>

typedef unsigned int u32;

// Problem dims (fixed by the reference)
#define BB   512
#define TT   80
#define DIN  512
#define HH   512
#define G4   2048      // 4*HH
#define NC   6625
#define SS   25
#define XW   7137      // DIN + NC  (w_ih row width)

// ---------------- scratch (device globals; no allocation allowed) ----------------
__device__ float g_bias4[G4];                       // b_ih + b_hh
__device__ float g_c[(size_t)BB * HH];              // cell state (exact fp32)
__device__ float g_gparts[2 * (size_t)BB * G4];     // split-K partials, gates GEMM
__device__ float g_sparts[4 * (size_t)BB * HH];     // split-K partials, s GEMM

// fp16 attention-path buffers (10-bit mantissa: 4x less quantization than bf16)
__device__ __half g_HprojH[(size_t)BB * TT * HH];   // 42 MB
__device__ __half g_inputsH[(size_t)BB * TT * DIN]; // 42 MB

// bf16 hi/lo GEMM operands
__device__ __nv_bfloat16 g_inputs2[(size_t)BB * TT * 1024]; // hi|lo, KH=512
__device__ __nv_bfloat16 g_i2h2[(size_t)HH * 1024];         // KH=512
__device__ __nv_bfloat16 g_genw2[(size_t)NC * 1024];        // KH=512
__device__ __nv_bfloat16 g_h2h2[(size_t)HH * 1024];         // KH=512
__device__ __nv_bfloat16 g_wcat2[(size_t)G4 * 2048];        // KH=1024: [w_ih[:,:512]|w_hh]
__device__ __nv_bfloat16 g_xcat2[(size_t)BB * 2048];        // KH=1024: [context|h]
__device__ __nv_bfloat16 g_c2[(size_t)BB * 1024];           // KH=512
__device__ __nv_bfloat16 g_hs2[(size_t)BB * SS * 1024];     // KH=512, row=b*25+t

__device__ __forceinline__ float sigf(float x) { return 1.f / (1.f + __expf(-x)); }
__device__ __forceinline__ float tanhfast(float x) {
    float e = __expf(2.f * x);
    return 1.f - 2.f / (e + 1.f);
}

// =================== bf16x3 tensor-core GEMM: C = A@B^T (+bias) ===================
// A2: [M][2*KHtot] bf16 (hi | lo). B2: [N][2*KHtot] same.
// blockIdx.z = split-K chunk over hi-k [z*kLenH, (z+1)*kLenH); 3 passes per chunk.
// gridDim.z>1 -> raw float partials at C + z*M*ldc (bias null).
// If Ch != null: write fp16 to Ch instead of float to C (z must be 1).
#define SMSTRIDE 24
#define STAGES   3

__device__ __forceinline__ void cpasync16(u32 dst, const void* src) {
    asm volatile("cp.async.cg.shared.global [%0], [%1], 16;" :: "r"(dst), "l"(src));
}

__global__ __launch_bounds__(256) void mma_bf16x3_nt(
    const __nv_bfloat16* __restrict__ A2, const __nv_bfloat16* __restrict__ B2,
    const float* __restrict__ bias, float* __restrict__ C,
    __half* __restrict__ Ch,
    int M, int N, int KHtot, int kLenH, int ldc)
{
    const int npp   = kLenH >> 4;
    const int ITERS = 3 * npp;
    const int z      = blockIdx.z;
    const int kStart = z * kLenH;
    const int rowK2  = 2 * KHtot;

    __shared__ __align__(128) __nv_bfloat16 As[STAGES][128 * SMSTRIDE];
    __shared__ __align__(128) __nv_bfloat16 Bs[STAGES][128 * SMSTRIDE];

    const int n0 = blockIdx.x * 128;
    const int m0 = blockIdx.y * 128;
    const int tid  = threadIdx.x;
    const int lrow = tid >> 1;
    const int lseg = tid & 1;

    const u32 asBase = (u32)__cvta_generic_to_shared(&As[0][0]);
    const u32 bsBase = (u32)__cvta_generic_to_shared(&Bs[0][0]);
    const u32 bufStride = 128 * SMSTRIDE * 2;
    const bool bval = (n0 + lrow) < N;

    const __nv_bfloat16* aSrcRow = A2 + (size_t)(m0 + lrow) * rowK2 + lseg * 8;
    const __nv_bfloat16* bSrcRow = B2 + (size_t)(n0 + lrow) * rowK2 + lseg * 8;
    const u32 dOff = (lrow * SMSTRIDE + lseg * 8) * 2;
    const u32 zero32 = 0;

    auto loadTiles = [&](int stg, int it) {
        int p = 0, kk = it;
        if (kk >= npp) { p++; kk -= npp; }
        if (kk >= npp) { p++; kk -= npp; }
        kk <<= 4;
        int acol = kStart + kk + ((p == 2) ? KHtot : 0);
        int bcol = kStart + kk + ((p == 1) ? KHtot : 0);
        u32 ad = asBase + stg * bufStride + dOff;
        u32 bd = bsBase + stg * bufStride + dOff;
        cpasync16(ad, aSrcRow + acol);
        if (bval) cpasync16(bd, bSrcRow + bcol);
        else      asm volatile("st.shared.v4.b32 [%0], {%1,%1,%1,%1};" :: "r"(bd), "r"(zero32));
        asm volatile("cp.async.commit_group;");
    };

    const int warp = tid >> 5, lane = tid & 31;
    const int wm = warp >> 1, wn = warp & 1;
    const int mbase = wm * 32, nbase = wn * 64;
    const u32 aFragOff = (((mbase + (lane & 15)) * SMSTRIDE) + (lane >> 4) * 8) * 2;
    const int sel = lane >> 3, lb = lane & 7;
    const u32 bFragOff =
        (((nbase + ((sel >> 1) & 1) * 8 + lb) * SMSTRIDE) + (sel & 1) * 8) * 2;

    float acc[2][8][4];
#pragma unroll
    for (int i = 0; i < 2; i++)
#pragma unroll
        for (int j = 0; j < 8; j++)
#pragma unroll
            for (int q = 0; q < 4; q++) acc[i][j][q] = 0.f;

    loadTiles(0, 0);
    if (ITERS > 1) loadTiles(1, 1);

    for (int it = 0; it < ITERS; ++it) {
        asm volatile("cp.async.wait_group %0;" :: "n"(STAGES - 2));
        __syncthreads();

        const int stg = it % STAGES;
        const u32 aB = asBase + stg * bufStride;
        const u32 bB = bsBase + stg * bufStride;

        u32 fa[2][4];
#pragma unroll
        for (int mf = 0; mf < 2; mf++) {
            u32 addr = aB + aFragOff + mf * (16 * SMSTRIDE * 2);
            asm volatile("ldmatrix.sync.aligned.m8n8.x4.shared.b16 {%0,%1,%2,%3}, [%4];"
                         : "=r"(fa[mf][0]), "=r"(fa[mf][1]), "=r"(fa[mf][2]), "=r"(fa[mf][3])
                         : "r"(addr));
        }
        u32 fb[8][2];
#pragma unroll
        for (int nn = 0; nn < 4; nn++) {
            u32 addr = bB + bFragOff + nn * (16 * SMSTRIDE * 2);
            asm volatile("ldmatrix.sync.aligned.m8n8.x4.shared.b16 {%0,%1,%2,%3}, [%4];"
                         : "=r"(fb[2*nn][0]), "=r"(fb[2*nn][1]),
                           "=r"(fb[2*nn+1][0]), "=r"(fb[2*nn+1][1])
                         : "r"(addr));
        }
#pragma unroll
        for (int mf = 0; mf < 2; mf++)
#pragma unroll
            for (int ni = 0; ni < 8; ni++) {
                asm volatile(
                    "mma.sync.aligned.m16n8k16.row.col.f32.bf16.bf16.f32 "
                    "{%0,%1,%2,%3}, {%4,%5,%6,%7}, {%8,%9}, {%0,%1,%2,%3};"
                    : "+f"(acc[mf][ni][0]), "+f"(acc[mf][ni][1]),
                      "+f"(acc[mf][ni][2]), "+f"(acc[mf][ni][3])
                    : "r"(fa[mf][0]), "r"(fa[mf][1]), "r"(fa[mf][2]), "r"(fa[mf][3]),
                      "r"(fb[ni][0]), "r"(fb[ni][1]));
            }

        int nx = it + STAGES - 1;
        if (nx < ITERS) loadTiles(nx % STAGES, nx);
    }

    // epilogue
    const int trow = lane >> 2, tcol = (lane & 3) * 2;
    const bool hasBias = (bias != nullptr);
#pragma unroll
    for (int mf = 0; mf < 2; mf++) {
        int r0 = m0 + mbase + mf * 16 + trow;
#pragma unroll
        for (int ni = 0; ni < 8; ni++) {
            int c0 = n0 + nbase + ni * 8 + tcol;
#pragma unroll
            for (int cc = 0; cc < 2; cc++) {
                int c = c0 + cc;
                if (c < N) {
                    if (Ch) {
                        Ch[(size_t)r0 * ldc + c]       = __float2half(acc[mf][ni][cc]);
                        Ch[(size_t)(r0 + 8) * ldc + c] = __float2half(acc[mf][ni][2 + cc]);
                    } else {
                        float bv = hasBias ? bias[c] : 0.f;
                        float* Cp = C + (size_t)z * (size_t)M * (size_t)ldc;
                        Cp[(size_t)r0 * ldc + c]       = acc[mf][ni][cc] + bv;
                        Cp[(size_t)(r0 + 8) * ldc + c] = acc[mf][ni][2 + cc] + bv;
                    }
                }
            }
        }
    }
}

// ------- inputs: fp32 -> bf16 hi/lo (GEMM operand) + fp16 copy (context dot) -------
__global__ void split_inputs_kernel(const float* __restrict__ src)
{
    int idx = blockIdx.x * 256 + threadIdx.x;       // < B*T*D
    if (idx >= BB * TT * DIN) return;
    int r = idx >> 9, c = idx & 511;
    float f = src[idx];
    __nv_bfloat16 hi = __float2bfloat16(f);
    g_inputs2[(size_t)r * 1024 + c]       = hi;
    g_inputs2[(size_t)r * 1024 + 512 + c] = __float2bfloat16(f - __bfloat162float(hi));
    g_inputsH[idx] = __float2half(f);
}

// ---------------- fp32 -> bf16 hi/lo split (generic) ----------------
__global__ void split_kernel(const float* __restrict__ src, __nv_bfloat16* __restrict__ dst,
                             int total, int cols)
{
    int idx = blockIdx.x * 256 + threadIdx.x;
    if (idx >= total) return;
    int r = idx / cols, c = idx - r * cols;
    float f = src[idx];
    __nv_bfloat16 hi = __float2bfloat16(f);
    float lo = f - __bfloat162float(hi);
    size_t base = (size_t)r * 2 * cols + c;
    dst[base] = hi;
    dst[base + cols] = __float2bfloat16(lo);
}

// ------- one-time: wcat2 split, bias4, h2h split -------
__global__ void pack_kernel(const float* __restrict__ w_ih, const float* __restrict__ w_hh,
                            const float* __restrict__ b_ih, const float* __restrict__ b_hh,
                            const float* __restrict__ h2h_w)
{
    int idx = blockIdx.x * 256 + threadIdx.x;       // < 2048*1024
    int n = idx >> 10, k = idx & 1023;
    float f = (k < 512) ? w_ih[(size_t)n * XW + k] : w_hh[n * 512 + (k - 512)];
    __nv_bfloat16 hi = __float2bfloat16(f);
    float lo = f - __bfloat162float(hi);
    g_wcat2[(size_t)n * 2048 + k]        = hi;
    g_wcat2[(size_t)n * 2048 + 1024 + k] = __float2bfloat16(lo);
    if (idx < G4) g_bias4[idx] = b_ih[idx] + b_hh[idx];
    if (idx < HH * HH) {
        int r = idx >> 9, c = idx & 511;
        float g = h2h_w[idx];
        __nv_bfloat16 ghi = __float2bfloat16(g);
        g_h2h2[(size_t)r * 1024 + c]       = ghi;
        g_h2h2[(size_t)r * 1024 + 512 + c] = __float2bfloat16(g - __bfloat162float(ghi));
    }
}

// ---------------- init: c = 0, c2 = 0, h-part of xcat2 = 0 ----------------
__global__ void init_kernel()
{
    int idx = blockIdx.x * 256 + threadIdx.x;       // < B*H
    int b = idx >> 9, hh = idx & 511;
    g_c[idx] = 0.f;
    __nv_bfloat16 z = __float2bfloat16(0.f);
    g_c2[(size_t)b * 1024 + hh]        = z;
    g_c2[(size_t)b * 1024 + 512 + hh]  = z;
    g_xcat2[(size_t)b * 2048 + 512 + hh]  = z;   // h hi
    g_xcat2[(size_t)b * 2048 + 1536 + hh] = z;   // h lo
}

// ---------------- fused attention (fp16 Hproj + fp16 inputs): one block per b -------
__global__ __launch_bounds__(256) void attention_kernel(
    const float* __restrict__ h2h_b, const float* __restrict__ score_w)
{
    const int b = blockIdx.x;
    const int tid = threadIdx.x;
    __shared__ __align__(16) float s_s[512];
    __shared__ __align__(16) float s_sc[512];
    __shared__ float s_e[96];

    for (int h = tid; h < 512; h += 256) {
        float v = h2h_b[h];
#pragma unroll
        for (int zz = 0; zz < 4; zz++)
            v += g_sparts[(size_t)zz * (BB * HH) + (size_t)b * HH + h];
        s_s[h] = v;
        s_sc[h] = score_w[h];
    }
    __syncthreads();

    const int w = tid >> 5, l = tid & 31;
    float svr[16], scr[16];
#pragma unroll
    for (int j = 0; j < 2; j++) {
        int fi = (j * 32 + l) * 2;
        *(float4*)&svr[j * 8]     = ((const float4*)s_s)[fi];
        *(float4*)&svr[j * 8 + 4] = ((const float4*)s_s)[fi + 1];
        *(float4*)&scr[j * 8]     = ((const float4*)s_sc)[fi];
        *(float4*)&scr[j * 8 + 4] = ((const float4*)s_sc)[fi + 1];
    }
    for (int t = w; t < TT; t += 8) {
        const float4* hrow = (const float4*)(g_HprojH + ((size_t)b * TT + t) * HH);
        float acc = 0.f;
#pragma unroll
        for (int j = 0; j < 2; j++) {
            float4 q = hrow[j * 32 + l];            // 8 fp16
            const __half2* hp2 = (const __half2*)&q;
#pragma unroll
            for (int p = 0; p < 4; p++) {
                float2 hv = __half22float2(hp2[p]);
                acc += scr[j * 8 + p * 2]     * tanhfast(hv.x + svr[j * 8 + p * 2]);
                acc += scr[j * 8 + p * 2 + 1] * tanhfast(hv.y + svr[j * 8 + p * 2 + 1]);
            }
        }
#pragma unroll
        for (int o = 16; o; o >>= 1) acc += __shfl_xor_sync(0xFFFFFFFFu, acc, o);
        if (l == 0) s_e[t] = acc;
    }
    __syncthreads();

    if (tid < 32) {
        float e0 = s_e[tid];
        float e1 = s_e[tid + 32];
        float e2 = (tid < 16) ? s_e[tid + 64] : -3.4e38f;
        float m = fmaxf(fmaxf(e0, e1), e2);
#pragma unroll
        for (int o = 16; o; o >>= 1) m = fmaxf(m, __shfl_xor_sync(0xFFFFFFFFu, m, o));
        float x0 = __expf(e0 - m), x1 = __expf(e1 - m);
        float x2 = (tid < 16) ? __expf(e2 - m) : 0.f;
        float sum = x0 + x1 + x2;
#pragma unroll
        for (int o = 16; o; o >>= 1) sum += __shfl_xor_sync(0xFFFFFFFFu, sum, o);
        float inv = 1.f / sum;
        s_e[tid] = x0 * inv; s_e[tid + 32] = x1 * inv;
        if (tid < 16) s_e[tid + 64] = x2 * inv;
    }
    __syncthreads();

    // context from fp16 inputs
    {
        float2 acc = make_float2(0.f, 0.f);
        const __half2* inp2 = (const __half2*)(g_inputsH + (size_t)b * TT * DIN);
        for (int t = 0; t < TT; t++) {
            float a = s_e[t];
            float2 v = __half22float2(inp2[t * 256 + tid]);
            acc.x += a * v.x; acc.y += a * v.y;
        }
        int d = 2 * tid;
        __nv_bfloat16 hx = __float2bfloat16(acc.x);
        __nv_bfloat16 hy = __float2bfloat16(acc.y);
        g_xcat2[(size_t)b * 2048 + d]            = hx;
        g_xcat2[(size_t)b * 2048 + d + 1]        = hy;
        g_xcat2[(size_t)b * 2048 + 1024 + d]     = __float2bfloat16(acc.x - __bfloat162float(hx));
        g_xcat2[(size_t)b * 2048 + 1024 + d + 1] = __float2bfloat16(acc.y - __bfloat162float(hy));
    }
}

// ---------------- LSTM pointwise ----------------
__global__ void lstm_pointwise(const float* __restrict__ w_ih, const int* __restrict__ targets,
                               int t)
{
    int idx = blockIdx.x * 256 + threadIdx.x;       // < B*H
    int b = idx >> 9, hh = idx & 511;
    int cls = targets[b * SS + t];
    const float* colp = w_ih + 512 + cls;

    float g4[4];
#pragma unroll
    for (int q = 0; q < 4; q++) {
        int gi = q * 512 + hh;
        float v = g_bias4[gi] + colp[(size_t)gi * XW];
#pragma unroll
        for (int zz = 0; zz < 2; zz++)
            v += g_gparts[(size_t)zz * (BB * G4) + (size_t)b * G4 + gi];
        g4[q] = v;
    }
    float ci = g_c[idx];
    float ig = sigf(g4[0]);
    float fg = sigf(g4[1]);
    float gg = tanhfast(g4[2]);
    float og = sigf(g4[3]);
    float cn = fg * ci + ig * gg;
    float hn = og * tanhfast(cn);
    g_c[idx] = cn;

    __nv_bfloat16 chi = __float2bfloat16(cn);
    g_c2[(size_t)b * 1024 + hh]       = chi;
    g_c2[(size_t)b * 1024 + 512 + hh] = __float2bfloat16(cn - __bfloat162float(chi));

    __nv_bfloat16 hhi = __float2bfloat16(hn);
    __nv_bfloat16 hlo = __float2bfloat16(hn - __bfloat162float(hhi));
    g_xcat2[(size_t)b * 2048 + 512 + hh]  = hhi;
    g_xcat2[(size_t)b * 2048 + 1536 + hh] = hlo;

    size_t hr = (size_t)b * SS + t;
    g_hs2[hr * 1024 + hh]       = hhi;
    g_hs2[hr * 1024 + 512 + hh] = hlo;
}

// ---------------- host launcher ----------------
extern "C" void kernel_launch(void* const* d_in, const int* in_sizes, int n_in,
                              void* d_out, int out_size)
{
    const float* inputs  = (const float*)d_in[0];
    const int*   targets = (const int*)  d_in[1];
    const float* i2h_w   = (const float*)d_in[2];
    const float* h2h_w   = (const float*)d_in[3];
    const float* h2h_b   = (const float*)d_in[4];
    const float* score_w = (const float*)d_in[5];
    const float* w_ih    = (const float*)d_in[6];
    const float* w_hh    = (const float*)d_in[7];
    const float* b_ih    = (const float*)d_in[8];
    const float* b_hh    = (const float*)d_in[9];
    const float* gen_w   = (const float*)d_in[10];
    const float* gen_b   = (const float*)d_in[11];
    float* out = (float*)d_out;

    static float *sparts = nullptr, *gparts;
    static __half *HprojH;
    static __nv_bfloat16 *inputs2, *i2h2, *genw2, *h2h2, *wcat2, *xcat2, *c2, *hs2;
    if (!sparts) {
        cudaGetSymbolAddress((void**)&sparts,  g_sparts);
        cudaGetSymbolAddress((void**)&gparts,  g_gparts);
        cudaGetSymbolAddress((void**)&HprojH,  g_HprojH);
        cudaGetSymbolAddress((void**)&inputs2, g_inputs2);
        cudaGetSymbolAddress((void**)&i2h2,    g_i2h2);
        cudaGetSymbolAddress((void**)&genw2,   g_genw2);
        cudaGetSymbolAddress((void**)&h2h2,    g_h2h2);
        cudaGetSymbolAddress((void**)&wcat2,   g_wcat2);
        cudaGetSymbolAddress((void**)&xcat2,   g_xcat2);
        cudaGetSymbolAddress((void**)&c2,      g_c2);
        cudaGetSymbolAddress((void**)&hs2,     g_hs2);
    }

    // Observed: ncu's captured launch idx 5 == our launch idx 3 (2 harness launches
    // precede ours). Put the Hproj MMA at idx 3 so next profile lands on it.
    split_inputs_kernel<<<(BB * TT * DIN + 255) / 256, 256>>>(inputs);          // 0
    split_kernel<<<(HH * DIN + 255) / 256, 256>>>(i2h_w, i2h2, HH * DIN, DIN);  // 1
    init_kernel<<<(BB * HH) / 256, 256>>>();                                    // 2
    // 3: Hproj (fp16 out) = inputs @ i2h_w^T   <-- ncu capture target
    mma_bf16x3_nt<<<dim3(HH / 128, (BB * TT) / 128, 1), 256>>>(
        inputs2, i2h2, nullptr, nullptr, HprojH, BB * TT, HH, 512, 512, HH);
    pack_kernel<<<(G4 * 1024) / 256, 256>>>(w_ih, w_hh, b_ih, b_hh, h2h_w);     // 4
    split_kernel<<<(NC * HH + 255) / 256, 256>>>(gen_w, genw2, NC * HH, HH);    // 5

    for (int t = 0; t < SS; t++) {
        // sparts = c @ h2h_w^T   (split-K: 4 chunks of 128 hi-cols)
        mma_bf16x3_nt<<<dim3(HH / 128, BB / 128, 4), 256>>>(
            c2, h2h2, nullptr, sparts, nullptr, BB, HH, 512, 128, HH);

        attention_kernel<<<BB, 256>>>(h2h_b, score_w);

        // gparts = xcat @ wcat^T  (split-K: 2 chunks of 512 hi-cols)
        mma_bf16x3_nt<<<dim3(G4 / 128, BB / 128, 2), 256>>>(
            xcat2, wcat2, nullptr, gparts, nullptr, BB, G4, 1024, 512, G4);

        lstm_pointwise<<<(BB * HH) / 256, 256>>>(w_ih, targets, t);
    }

    // probs = hs @ gen_w^T + gen_b
    mma_bf16x3_nt<<<dim3((NC + 127) / 128, (BB * SS) / 128, 1), 256>>>(
        hs2, genw2, gen_b, out, nullptr, BB * SS, NC, 512, 512, NC);
}

// round 14
// speedup vs baseline: 1.2014x; 1.2014x over previous
#include <cuda_runtime.h>
#include <cuda_bf16.h>
#include <cuda_fp16.h>
#include <math.h>

typedef unsigned int u32;

// Problem dims (fixed by the reference)
#define BB   512
#define TT   80
#define DIN  512
#define HH   512
#define G4   2048      // 4*HH
#define NC   6625
#define SS   25
#define XW   7137      // DIN + NC  (w_ih row width)

// ---------------- scratch (device globals; no allocation allowed) ----------------
__device__ float g_bias4[G4];
__device__ float g_c[(size_t)BB * HH];              // cell state (exact fp32)
__device__ float g_gparts[2 * (size_t)BB * G4];     // split-K partials, gates GEMM
__device__ float g_sparts[8 * (size_t)BB * HH];     // split-K partials, s GEMM

// fp16 attention-path buffers
__device__ __half g_HprojH[(size_t)BB * TT * HH];   // 42 MB
__device__ __half g_inputsH[(size_t)BB * TT * DIN]; // 42 MB

// bf16 hi/lo GEMM operands
__device__ __nv_bfloat16 g_inputs2[(size_t)BB * TT * 1024]; // hi|lo, KH=512
__device__ __nv_bfloat16 g_i2h2[(size_t)HH * 1024];
__device__ __nv_bfloat16 g_genw2[(size_t)NC * 1024];
__device__ __nv_bfloat16 g_h2h2[(size_t)HH * 1024];
__device__ __nv_bfloat16 g_wcat2[(size_t)G4 * 2048];        // KH=1024
__device__ __nv_bfloat16 g_xcat2[(size_t)BB * 2048];        // KH=1024
__device__ __nv_bfloat16 g_c2[(size_t)BB * 1024];
__device__ __nv_bfloat16 g_hs2[(size_t)BB * SS * 1024];

__device__ __forceinline__ float sigf(float x) { return 1.f / (1.f + __expf(-x)); }
__device__ __forceinline__ float tanhfast(float x) {
    float e = __expf(2.f * x);
    return 1.f - 2.f / (e + 1.f);
}
__device__ __forceinline__ void cpasync16(u32 dst, const void* src) {
    asm volatile("cp.async.cg.shared.global [%0], [%1], 16;" :: "r"(dst), "l"(src));
}

// =================== bf16x3 tensor-core GEMM: C = A@B^T (+bias) ===================
// A2: [M][2*KHtot] bf16 (hi | lo). B2: [N][2*KHtot] same.
// blockIdx.z = split-K chunk over hi-k [z*kLenH, (z+1)*kLenH); 3 passes per chunk.
// K=32 stages (two k16 mma sub-steps per barrier), 3-stage cp.async pipeline.
// SMEM layout: row stride 64B (32 bf16), 16B chunk c at ((c ^ ((row>>1)&3)) * 16)
// — XOR swizzle gives conflict-free cp.async stores AND ldmatrix reads, no padding.
// gridDim.z>1 -> raw float partials at C + z*M*ldc (bias null).
// If Ch != null: write fp16 to Ch (z must be 1).
__global__ __launch_bounds__(256) void mma_bf16x3_nt(
    const __nv_bfloat16* __restrict__ A2, const __nv_bfloat16* __restrict__ B2,
    const float* __restrict__ bias, float* __restrict__ C,
    __half* __restrict__ Ch,
    int M, int N, int KHtot, int kLenH, int ldc)
{
    const int npp   = kLenH >> 5;        // K32 iters per pass
    const int ITERS = 3 * npp;
    const int z      = blockIdx.z;
    const int kStart = z * kLenH;
    const int rowK2  = 2 * KHtot;

    // 3 stages x (A 8KB + B 8KB) = 49152 B exactly (static smem limit)
    __shared__ __align__(128) __nv_bfloat16 As[3][128 * 32];
    __shared__ __align__(128) __nv_bfloat16 Bs[3][128 * 32];

    const int n0 = blockIdx.x * 128;
    const int m0 = blockIdx.y * 128;
    const int tid  = threadIdx.x;

    const u32 asBase = (u32)__cvta_generic_to_shared(&As[0][0]);
    const u32 bsBase = (u32)__cvta_generic_to_shared(&Bs[0][0]);

    // ---- load geometry: thread -> row (tid>>1), chunk pair h = tid&1 ----
    const int row = tid >> 1, h = tid & 1;
    const bool bval = (n0 + row) < N;
    const __nv_bfloat16* aSrcRow = A2 + (size_t)(m0 + row) * rowK2 + h * 16;
    const __nv_bfloat16* bSrcRow = B2 + (size_t)(n0 + row) * rowK2 + h * 16;
    const int swzr = (row >> 1) & 3;
    const u32 dA0 = row * 64 + (((2 * h)     ^ swzr) * 16);
    const u32 dA1 = row * 64 + (((2 * h + 1) ^ swzr) * 16);
    const u32 zero32 = 0;

    auto loadTiles = [&](int stg, int it) {
        int p = 0, kk = it;
        if (kk >= npp) { p++; kk -= npp; }
        if (kk >= npp) { p++; kk -= npp; }
        kk <<= 5;
        int acol = kStart + kk + ((p == 2) ? KHtot : 0);
        int bcol = kStart + kk + ((p == 1) ? KHtot : 0);
        u32 ab = asBase + stg * 8192;
        u32 bb = bsBase + stg * 8192;
        cpasync16(ab + dA0, aSrcRow + acol);
        cpasync16(ab + dA1, aSrcRow + acol + 8);
        if (bval) {
            cpasync16(bb + dA0, bSrcRow + bcol);
            cpasync16(bb + dA1, bSrcRow + bcol + 8);
        } else {
            asm volatile("st.shared.v4.b32 [%0], {%1,%1,%1,%1};" :: "r"(bb + dA0), "r"(zero32));
            asm volatile("st.shared.v4.b32 [%0], {%1,%1,%1,%1};" :: "r"(bb + dA1), "r"(zero32));
        }
        asm volatile("cp.async.commit_group;");
    };

    // ---- fragment addressing (validated lane maps from R6, new swizzle layout) ----
    const int warp = tid >> 5, lane = tid & 31;
    const int wm = warp >> 1, wn = warp & 1;
    const int mbase = wm * 32, nbase = wn * 64;

    u32 aOff[2][2];
#pragma unroll
    for (int mf = 0; mf < 2; mf++) {
        int rA = mbase + mf * 16 + (lane & 15);
        int kc = lane >> 4;
        int sw = (rA >> 1) & 3;
#pragma unroll
        for (int ks = 0; ks < 2; ks++)
            aOff[mf][ks] = rA * 64 + (((ks * 2 + kc) ^ sw) * 16);
    }
    const int sel = lane >> 3, lb = lane & 7;
    u32 bOff[4][2];
#pragma unroll
    for (int nn = 0; nn < 4; nn++) {
        int rB = nbase + nn * 16 + ((sel >> 1) & 1) * 8 + lb;
        int kc = sel & 1;
        int sw = (rB >> 1) & 3;
#pragma unroll
        for (int ks = 0; ks < 2; ks++)
            bOff[nn][ks] = rB * 64 + (((ks * 2 + kc) ^ sw) * 16);
    }

    float acc[2][8][4];
#pragma unroll
    for (int i = 0; i < 2; i++)
#pragma unroll
        for (int j = 0; j < 8; j++)
#pragma unroll
            for (int q = 0; q < 4; q++) acc[i][j][q] = 0.f;

    loadTiles(0, 0);
    if (ITERS > 1) loadTiles(1, 1);

    for (int it = 0; it < ITERS; ++it) {
        // stage it%3 must be complete; allow 1 pending ONLY if a newer load exists
        if (it + 1 < ITERS) asm volatile("cp.async.wait_group 1;");
        else                asm volatile("cp.async.wait_group 0;");
        __syncthreads();

        // prefetch stage (it+2)%3 (overwrites stage read at it-1; barrier-protected)
        int nx = it + 2;
        if (nx < ITERS) loadTiles(nx % 3, nx);

        const int stg = it % 3;
        const u32 aB = asBase + stg * 8192;
        const u32 bB = bsBase + stg * 8192;

#pragma unroll
        for (int ks = 0; ks < 2; ks++) {
            u32 fa[2][4];
#pragma unroll
            for (int mf = 0; mf < 2; mf++) {
                asm volatile("ldmatrix.sync.aligned.m8n8.x4.shared.b16 {%0,%1,%2,%3}, [%4];"
                             : "=r"(fa[mf][0]), "=r"(fa[mf][1]), "=r"(fa[mf][2]), "=r"(fa[mf][3])
                             : "r"(aB + aOff[mf][ks]));
            }
            u32 fb[8][2];
#pragma unroll
            for (int nn = 0; nn < 4; nn++) {
                asm volatile("ldmatrix.sync.aligned.m8n8.x4.shared.b16 {%0,%1,%2,%3}, [%4];"
                             : "=r"(fb[2*nn][0]), "=r"(fb[2*nn][1]),
                               "=r"(fb[2*nn+1][0]), "=r"(fb[2*nn+1][1])
                             : "r"(bB + bOff[nn][ks]));
            }
#pragma unroll
            for (int mf = 0; mf < 2; mf++)
#pragma unroll
                for (int ni = 0; ni < 8; ni++) {
                    asm volatile(
                        "mma.sync.aligned.m16n8k16.row.col.f32.bf16.bf16.f32 "
                        "{%0,%1,%2,%3}, {%4,%5,%6,%7}, {%8,%9}, {%0,%1,%2,%3};"
                        : "+f"(acc[mf][ni][0]), "+f"(acc[mf][ni][1]),
                          "+f"(acc[mf][ni][2]), "+f"(acc[mf][ni][3])
                        : "r"(fa[mf][0]), "r"(fa[mf][1]), "r"(fa[mf][2]), "r"(fa[mf][3]),
                          "r"(fb[ni][0]), "r"(fb[ni][1]));
                }
        }
    }

    // epilogue
    const int trow = lane >> 2, tcol = (lane & 3) * 2;
    const bool hasBias = (bias != nullptr);
#pragma unroll
    for (int mf = 0; mf < 2; mf++) {
        int r0 = m0 + mbase + mf * 16 + trow;
#pragma unroll
        for (int ni = 0; ni < 8; ni++) {
            int c0 = n0 + nbase + ni * 8 + tcol;
#pragma unroll
            for (int cc = 0; cc < 2; cc++) {
                int c = c0 + cc;
                if (c < N) {
                    if (Ch) {
                        Ch[(size_t)r0 * ldc + c]       = __float2half(acc[mf][ni][cc]);
                        Ch[(size_t)(r0 + 8) * ldc + c] = __float2half(acc[mf][ni][2 + cc]);
                    } else {
                        float bv = hasBias ? bias[c] : 0.f;
                        float* Cp = C + (size_t)z * (size_t)M * (size_t)ldc;
                        Cp[(size_t)r0 * ldc + c]       = acc[mf][ni][cc] + bv;
                        Cp[(size_t)(r0 + 8) * ldc + c] = acc[mf][ni][2 + cc] + bv;
                    }
                }
            }
        }
    }
}

// ------- inputs: fp32 -> bf16 hi/lo + fp16 copy -------
__global__ void split_inputs_kernel(const float* __restrict__ src)
{
    int idx = blockIdx.x * 256 + threadIdx.x;
    if (idx >= BB * TT * DIN) return;
    int r = idx >> 9, c = idx & 511;
    float f = src[idx];
    __nv_bfloat16 hi = __float2bfloat16(f);
    g_inputs2[(size_t)r * 1024 + c]       = hi;
    g_inputs2[(size_t)r * 1024 + 512 + c] = __float2bfloat16(f - __bfloat162float(hi));
    g_inputsH[idx] = __float2half(f);
}

__global__ void split_kernel(const float* __restrict__ src, __nv_bfloat16* __restrict__ dst,
                             int total, int cols)
{
    int idx = blockIdx.x * 256 + threadIdx.x;
    if (idx >= total) return;
    int r = idx / cols, c = idx - r * cols;
    float f = src[idx];
    __nv_bfloat16 hi = __float2bfloat16(f);
    float lo = f - __bfloat162float(hi);
    size_t base = (size_t)r * 2 * cols + c;
    dst[base] = hi;
    dst[base + cols] = __float2bfloat16(lo);
}

__global__ void pack_kernel(const float* __restrict__ w_ih, const float* __restrict__ w_hh,
                            const float* __restrict__ b_ih, const float* __restrict__ b_hh,
                            const float* __restrict__ h2h_w)
{
    int idx = blockIdx.x * 256 + threadIdx.x;
    int n = idx >> 10, k = idx & 1023;
    float f = (k < 512) ? w_ih[(size_t)n * XW + k] : w_hh[n * 512 + (k - 512)];
    __nv_bfloat16 hi = __float2bfloat16(f);
    float lo = f - __bfloat162float(hi);
    g_wcat2[(size_t)n * 2048 + k]        = hi;
    g_wcat2[(size_t)n * 2048 + 1024 + k] = __float2bfloat16(lo);
    if (idx < G4) g_bias4[idx] = b_ih[idx] + b_hh[idx];
    if (idx < HH * HH) {
        int r = idx >> 9, c = idx & 511;
        float g = h2h_w[idx];
        __nv_bfloat16 ghi = __float2bfloat16(g);
        g_h2h2[(size_t)r * 1024 + c]       = ghi;
        g_h2h2[(size_t)r * 1024 + 512 + c] = __float2bfloat16(g - __bfloat162float(ghi));
    }
}

__global__ void init_kernel()
{
    int idx = blockIdx.x * 256 + threadIdx.x;
    int b = idx >> 9, hh = idx & 511;
    g_c[idx] = 0.f;
    __nv_bfloat16 z = __float2bfloat16(0.f);
    g_c2[(size_t)b * 1024 + hh]        = z;
    g_c2[(size_t)b * 1024 + 512 + hh]  = z;
    g_xcat2[(size_t)b * 2048 + 512 + hh]  = z;
    g_xcat2[(size_t)b * 2048 + 1536 + hh] = z;
}

// ---------------- fused attention (fp16 Hproj + fp16 inputs) ----------------
__global__ __launch_bounds__(256) void attention_kernel(
    const float* __restrict__ h2h_b, const float* __restrict__ score_w)
{
    const int b = blockIdx.x;
    const int tid = threadIdx.x;
    __shared__ __align__(16) float s_s[512];
    __shared__ __align__(16) float s_sc[512];
    __shared__ float s_e[96];

    for (int h = tid; h < 512; h += 256) {
        float v = h2h_b[h];
#pragma unroll
        for (int zz = 0; zz < 8; zz++)
            v += g_sparts[(size_t)zz * (BB * HH) + (size_t)b * HH + h];
        s_s[h] = v;
        s_sc[h] = score_w[h];
    }
    __syncthreads();

    const int w = tid >> 5, l = tid & 31;
    float svr[16], scr[16];
#pragma unroll
    for (int j = 0; j < 2; j++) {
        int fi = (j * 32 + l) * 2;
        *(float4*)&svr[j * 8]     = ((const float4*)s_s)[fi];
        *(float4*)&svr[j * 8 + 4] = ((const float4*)s_s)[fi + 1];
        *(float4*)&scr[j * 8]     = ((const float4*)s_sc)[fi];
        *(float4*)&scr[j * 8 + 4] = ((const float4*)s_sc)[fi + 1];
    }
    for (int t = w; t < TT; t += 8) {
        const float4* hrow = (const float4*)(g_HprojH + ((size_t)b * TT + t) * HH);
        float acc = 0.f;
#pragma unroll
        for (int j = 0; j < 2; j++) {
            float4 q = hrow[j * 32 + l];
            const __half2* hp2 = (const __half2*)&q;
#pragma unroll
            for (int p = 0; p < 4; p++) {
                float2 hv = __half22float2(hp2[p]);
                acc += scr[j * 8 + p * 2]     * tanhfast(hv.x + svr[j * 8 + p * 2]);
                acc += scr[j * 8 + p * 2 + 1] * tanhfast(hv.y + svr[j * 8 + p * 2 + 1]);
            }
        }
#pragma unroll
        for (int o = 16; o; o >>= 1) acc += __shfl_xor_sync(0xFFFFFFFFu, acc, o);
        if (l == 0) s_e[t] = acc;
    }
    __syncthreads();

    if (tid < 32) {
        float e0 = s_e[tid];
        float e1 = s_e[tid + 32];
        float e2 = (tid < 16) ? s_e[tid + 64] : -3.4e38f;
        float m = fmaxf(fmaxf(e0, e1), e2);
#pragma unroll
        for (int o = 16; o; o >>= 1) m = fmaxf(m, __shfl_xor_sync(0xFFFFFFFFu, m, o));
        float x0 = __expf(e0 - m), x1 = __expf(e1 - m);
        float x2 = (tid < 16) ? __expf(e2 - m) : 0.f;
        float sum = x0 + x1 + x2;
#pragma unroll
        for (int o = 16; o; o >>= 1) sum += __shfl_xor_sync(0xFFFFFFFFu, sum, o);
        float inv = 1.f / sum;
        s_e[tid] = x0 * inv; s_e[tid + 32] = x1 * inv;
        if (tid < 16) s_e[tid + 64] = x2 * inv;
    }
    __syncthreads();

    {
        float2 acc = make_float2(0.f, 0.f);
        const __half2* inp2 = (const __half2*)(g_inputsH + (size_t)b * TT * DIN);
        for (int t = 0; t < TT; t++) {
            float a = s_e[t];
            float2 v = __half22float2(inp2[t * 256 + tid]);
            acc.x += a * v.x; acc.y += a * v.y;
        }
        int d = 2 * tid;
        __nv_bfloat16 hx = __float2bfloat16(acc.x);
        __nv_bfloat16 hy = __float2bfloat16(acc.y);
        g_xcat2[(size_t)b * 2048 + d]            = hx;
        g_xcat2[(size_t)b * 2048 + d + 1]        = hy;
        g_xcat2[(size_t)b * 2048 + 1024 + d]     = __float2bfloat16(acc.x - __bfloat162float(hx));
        g_xcat2[(size_t)b * 2048 + 1024 + d + 1] = __float2bfloat16(acc.y - __bfloat162float(hy));
    }
}

// ---------------- LSTM pointwise ----------------
__global__ void lstm_pointwise(const float* __restrict__ w_ih, const int* __restrict__ targets,
                               int t)
{
    int idx = blockIdx.x * 256 + threadIdx.x;
    int b = idx >> 9, hh = idx & 511;
    int cls = targets[b * SS + t];
    const float* colp = w_ih + 512 + cls;

    float g4[4];
#pragma unroll
    for (int q = 0; q < 4; q++) {
        int gi = q * 512 + hh;
        float v = g_bias4[gi] + colp[(size_t)gi * XW];
#pragma unroll
        for (int zz = 0; zz < 2; zz++)
            v += g_gparts[(size_t)zz * (BB * G4) + (size_t)b * G4 + gi];
        g4[q] = v;
    }
    float ci = g_c[idx];
    float ig = sigf(g4[0]);
    float fg = sigf(g4[1]);
    float gg = tanhfast(g4[2]);
    float og = sigf(g4[3]);
    float cn = fg * ci + ig * gg;
    float hn = og * tanhfast(cn);
    g_c[idx] = cn;

    __nv_bfloat16 chi = __float2bfloat16(cn);
    g_c2[(size_t)b * 1024 + hh]       = chi;
    g_c2[(size_t)b * 1024 + 512 + hh] = __float2bfloat16(cn - __bfloat162float(chi));

    __nv_bfloat16 hhi = __float2bfloat16(hn);
    __nv_bfloat16 hlo = __float2bfloat16(hn - __bfloat162float(hhi));
    g_xcat2[(size_t)b * 2048 + 512 + hh]  = hhi;
    g_xcat2[(size_t)b * 2048 + 1536 + hh] = hlo;

    size_t hr = (size_t)b * SS + t;
    g_hs2[hr * 1024 + hh]       = hhi;
    g_hs2[hr * 1024 + 512 + hh] = hlo;
}

// ---------------- host launcher ----------------
extern "C" void kernel_launch(void* const* d_in, const int* in_sizes, int n_in,
                              void* d_out, int out_size)
{
    const float* inputs  = (const float*)d_in[0];
    const int*   targets = (const int*)  d_in[1];
    const float* i2h_w   = (const float*)d_in[2];
    const float* h2h_w   = (const float*)d_in[3];
    const float* h2h_b   = (const float*)d_in[4];
    const float* score_w = (const float*)d_in[5];
    const float* w_ih    = (const float*)d_in[6];
    const float* w_hh    = (const float*)d_in[7];
    const float* b_ih    = (const float*)d_in[8];
    const float* b_hh    = (const float*)d_in[9];
    const float* gen_w   = (const float*)d_in[10];
    const float* gen_b   = (const float*)d_in[11];
    float* out = (float*)d_out;

    static float *sparts = nullptr, *gparts;
    static __half *HprojH;
    static __nv_bfloat16 *inputs2, *i2h2, *genw2, *h2h2, *wcat2, *xcat2, *c2, *hs2;
    if (!sparts) {
        cudaGetSymbolAddress((void**)&sparts,  g_sparts);
        cudaGetSymbolAddress((void**)&gparts,  g_gparts);
        cudaGetSymbolAddress((void**)&HprojH,  g_HprojH);
        cudaGetSymbolAddress((void**)&inputs2, g_inputs2);
        cudaGetSymbolAddress((void**)&i2h2,    g_i2h2);
        cudaGetSymbolAddress((void**)&genw2,   g_genw2);
        cudaGetSymbolAddress((void**)&h2h2,    g_h2h2);
        cudaGetSymbolAddress((void**)&wcat2,   g_wcat2);
        cudaGetSymbolAddress((void**)&xcat2,   g_xcat2);
        cudaGetSymbolAddress((void**)&c2,      g_c2);
        cudaGetSymbolAddress((void**)&hs2,     g_hs2);
    }

    // ncu captured-launch idx 5 == our idx 3: keep Hproj MMA there.
    split_inputs_kernel<<<(BB * TT * DIN + 255) / 256, 256>>>(inputs);          // 0
    split_kernel<<<(HH * DIN + 255) / 256, 256>>>(i2h_w, i2h2, HH * DIN, DIN);  // 1
    init_kernel<<<(BB * HH) / 256, 256>>>();                                    // 2
    // 3: Hproj (fp16 out) = inputs @ i2h_w^T   <-- ncu capture target
    mma_bf16x3_nt<<<dim3(HH / 128, (BB * TT) / 128, 1), 256>>>(
        inputs2, i2h2, nullptr, nullptr, HprojH, BB * TT, HH, 512, 512, HH);
    pack_kernel<<<(G4 * 1024) / 256, 256>>>(w_ih, w_hh, b_ih, b_hh, h2h_w);     // 4
    split_kernel<<<(NC * HH + 255) / 256, 256>>>(gen_w, genw2, NC * HH, HH);    // 5

    for (int t = 0; t < SS; t++) {
        // sparts = c @ h2h_w^T   (split-K: 8 chunks of 64 hi-cols -> 128 blocks)
        mma_bf16x3_nt<<<dim3(HH / 128, BB / 128, 8), 256>>>(
            c2, h2h2, nullptr, sparts, nullptr, BB, HH, 512, 64, HH);

        attention_kernel<<<BB, 256>>>(h2h_b, score_w);

        // gparts = xcat @ wcat^T  (split-K: 2 chunks of 512 hi-cols)
        mma_bf16x3_nt<<<dim3(G4 / 128, BB / 128, 2), 256>>>(
            xcat2, wcat2, nullptr, gparts, nullptr, BB, G4, 1024, 512, G4);

        lstm_pointwise<<<(BB * HH) / 256, 256>>>(w_ih, targets, t);
    }

    // probs = hs @ gen_w^T + gen_b
    mma_bf16x3_nt<<<dim3((NC + 127) / 128, (BB * SS) / 128, 1), 256>>>(
        hs2, genw2, gen_b, out, nullptr, BB * SS, NC, 512, 512, NC);
}

// round 15
// speedup vs baseline: 1.2015x; 1.0000x over previous
#include <cuda_runtime.h>
#include <cuda_bf16.h>
#include <cuda_fp16.h>
#include <math.h>

typedef unsigned int u32;

// Problem dims (fixed by the reference)
#define BB   512
#define TT   80
#define DIN  512
#define HH   512
#define G4   2048      // 4*HH
#define NC   6625
#define SS   25
#define XW   7137      // DIN + NC  (w_ih row width)

// ---------------- scratch (device globals; no allocation allowed) ----------------
__device__ float g_bias4[G4];
__device__ float g_c[(size_t)BB * HH];              // cell state (exact fp32)
__device__ float g_gparts[2 * (size_t)BB * G4];     // split-K partials, gates GEMM
__device__ float g_sparts[8 * (size_t)BB * HH];     // split-K partials, s GEMM

// fp16 attention-path buffers
__device__ __half g_HprojH[(size_t)BB * TT * HH];   // 42 MB
__device__ __half g_inputsH[(size_t)BB * TT * DIN]; // 42 MB

// bf16 hi/lo GEMM operands
__device__ __nv_bfloat16 g_inputs2[(size_t)BB * TT * 1024]; // hi|lo, KH=512
__device__ __nv_bfloat16 g_i2h2[(size_t)HH * 1024];
__device__ __nv_bfloat16 g_genw2[(size_t)NC * 1024];
__device__ __nv_bfloat16 g_h2h2[(size_t)HH * 1024];
__device__ __nv_bfloat16 g_wcat2[(size_t)G4 * 2048];        // KH=1024
__device__ __nv_bfloat16 g_xcat2[(size_t)BB * 2048];        // KH=1024
__device__ __nv_bfloat16 g_c2[(size_t)BB * 1024];
__device__ __nv_bfloat16 g_hs2[(size_t)BB * SS * 1024];

__device__ __forceinline__ float sigf(float x) { return 1.f / (1.f + __expf(-x)); }
__device__ __forceinline__ float tanhfast(float x) {
    float e = __expf(2.f * x);
    return 1.f - 2.f / (e + 1.f);
}
__device__ __forceinline__ void cpasync16(u32 dst, const void* src) {
    asm volatile("cp.async.cg.shared.global [%0], [%1], 16;" :: "r"(dst), "l"(src));
}

// =================== bf16x3 tensor-core GEMM: C = A@B^T (+bias) ===================
// A2: [M][2*KHtot] bf16 (hi | lo). B2: [N][2*KHtot] same.
// blockIdx.z = split-K chunk over hi-k [z*kLenH, (z+1)*kLenH); 3 passes per chunk.
// K=32 stages (two k16 mma sub-steps per barrier), 3-stage cp.async pipeline.
// SMEM layout: row stride 64B (32 bf16), 16B chunk c at ((c ^ ((row>>1)&3)) * 16)
// — XOR swizzle gives conflict-free cp.async stores AND ldmatrix reads, no padding.
// gridDim.z>1 -> raw float partials at C + z*M*ldc (bias null).
// If Ch != null: write fp16 to Ch (z must be 1).
__global__ __launch_bounds__(256) void mma_bf16x3_nt(
    const __nv_bfloat16* __restrict__ A2, const __nv_bfloat16* __restrict__ B2,
    const float* __restrict__ bias, float* __restrict__ C,
    __half* __restrict__ Ch,
    int M, int N, int KHtot, int kLenH, int ldc)
{
    const int npp   = kLenH >> 5;        // K32 iters per pass
    const int ITERS = 3 * npp;
    const int z      = blockIdx.z;
    const int kStart = z * kLenH;
    const int rowK2  = 2 * KHtot;

    // 3 stages x (A 8KB + B 8KB) = 49152 B exactly (static smem limit)
    __shared__ __align__(128) __nv_bfloat16 As[3][128 * 32];
    __shared__ __align__(128) __nv_bfloat16 Bs[3][128 * 32];

    const int n0 = blockIdx.x * 128;
    const int m0 = blockIdx.y * 128;
    const int tid  = threadIdx.x;

    const u32 asBase = (u32)__cvta_generic_to_shared(&As[0][0]);
    const u32 bsBase = (u32)__cvta_generic_to_shared(&Bs[0][0]);

    // ---- load geometry: thread -> row (tid>>1), chunk pair h = tid&1 ----
    const int row = tid >> 1, h = tid & 1;
    const bool bval = (n0 + row) < N;
    const __nv_bfloat16* aSrcRow = A2 + (size_t)(m0 + row) * rowK2 + h * 16;
    const __nv_bfloat16* bSrcRow = B2 + (size_t)(n0 + row) * rowK2 + h * 16;
    const int swzr = (row >> 1) & 3;
    const u32 dA0 = row * 64 + (((2 * h)     ^ swzr) * 16);
    const u32 dA1 = row * 64 + (((2 * h + 1) ^ swzr) * 16);
    const u32 zero32 = 0;

    auto loadTiles = [&](int stg, int it) {
        int p = 0, kk = it;
        if (kk >= npp) { p++; kk -= npp; }
        if (kk >= npp) { p++; kk -= npp; }
        kk <<= 5;
        int acol = kStart + kk + ((p == 2) ? KHtot : 0);
        int bcol = kStart + kk + ((p == 1) ? KHtot : 0);
        u32 ab = asBase + stg * 8192;
        u32 bb = bsBase + stg * 8192;
        cpasync16(ab + dA0, aSrcRow + acol);
        cpasync16(ab + dA1, aSrcRow + acol + 8);
        if (bval) {
            cpasync16(bb + dA0, bSrcRow + bcol);
            cpasync16(bb + dA1, bSrcRow + bcol + 8);
        } else {
            asm volatile("st.shared.v4.b32 [%0], {%1,%1,%1,%1};" :: "r"(bb + dA0), "r"(zero32));
            asm volatile("st.shared.v4.b32 [%0], {%1,%1,%1,%1};" :: "r"(bb + dA1), "r"(zero32));
        }
        asm volatile("cp.async.commit_group;");
    };

    // ---- fragment addressing (validated lane maps from R6, new swizzle layout) ----
    const int warp = tid >> 5, lane = tid & 31;
    const int wm = warp >> 1, wn = warp & 1;
    const int mbase = wm * 32, nbase = wn * 64;

    u32 aOff[2][2];
#pragma unroll
    for (int mf = 0; mf < 2; mf++) {
        int rA = mbase + mf * 16 + (lane & 15);
        int kc = lane >> 4;
        int sw = (rA >> 1) & 3;
#pragma unroll
        for (int ks = 0; ks < 2; ks++)
            aOff[mf][ks] = rA * 64 + (((ks * 2 + kc) ^ sw) * 16);
    }
    const int sel = lane >> 3, lb = lane & 7;
    u32 bOff[4][2];
#pragma unroll
    for (int nn = 0; nn < 4; nn++) {
        int rB = nbase + nn * 16 + ((sel >> 1) & 1) * 8 + lb;
        int kc = sel & 1;
        int sw = (rB >> 1) & 3;
#pragma unroll
        for (int ks = 0; ks < 2; ks++)
            bOff[nn][ks] = rB * 64 + (((ks * 2 + kc) ^ sw) * 16);
    }

    float acc[2][8][4];
#pragma unroll
    for (int i = 0; i < 2; i++)
#pragma unroll
        for (int j = 0; j < 8; j++)
#pragma unroll
            for (int q = 0; q < 4; q++) acc[i][j][q] = 0.f;

    loadTiles(0, 0);
    if (ITERS > 1) loadTiles(1, 1);

    for (int it = 0; it < ITERS; ++it) {
        // stage it%3 must be complete; allow 1 pending ONLY if a newer load exists
        if (it + 1 < ITERS) asm volatile("cp.async.wait_group 1;");
        else                asm volatile("cp.async.wait_group 0;");
        __syncthreads();

        // prefetch stage (it+2)%3 (overwrites stage read at it-1; barrier-protected)
        int nx = it + 2;
        if (nx < ITERS) loadTiles(nx % 3, nx);

        const int stg = it % 3;
        const u32 aB = asBase + stg * 8192;
        const u32 bB = bsBase + stg * 8192;

#pragma unroll
        for (int ks = 0; ks < 2; ks++) {
            u32 fa[2][4];
#pragma unroll
            for (int mf = 0; mf < 2; mf++) {
                asm volatile("ldmatrix.sync.aligned.m8n8.x4.shared.b16 {%0,%1,%2,%3}, [%4];"
                             : "=r"(fa[mf][0]), "=r"(fa[mf][1]), "=r"(fa[mf][2]), "=r"(fa[mf][3])
                             : "r"(aB + aOff[mf][ks]));
            }
            u32 fb[8][2];
#pragma unroll
            for (int nn = 0; nn < 4; nn++) {
                asm volatile("ldmatrix.sync.aligned.m8n8.x4.shared.b16 {%0,%1,%2,%3}, [%4];"
                             : "=r"(fb[2*nn][0]), "=r"(fb[2*nn][1]),
                               "=r"(fb[2*nn+1][0]), "=r"(fb[2*nn+1][1])
                             : "r"(bB + bOff[nn][ks]));
            }
#pragma unroll
            for (int mf = 0; mf < 2; mf++)
#pragma unroll
                for (int ni = 0; ni < 8; ni++) {
                    asm volatile(
                        "mma.sync.aligned.m16n8k16.row.col.f32.bf16.bf16.f32 "
                        "{%0,%1,%2,%3}, {%4,%5,%6,%7}, {%8,%9}, {%0,%1,%2,%3};"
                        : "+f"(acc[mf][ni][0]), "+f"(acc[mf][ni][1]),
                          "+f"(acc[mf][ni][2]), "+f"(acc[mf][ni][3])
                        : "r"(fa[mf][0]), "r"(fa[mf][1]), "r"(fa[mf][2]), "r"(fa[mf][3]),
                          "r"(fb[ni][0]), "r"(fb[ni][1]));
                }
        }
    }

    // epilogue
    const int trow = lane >> 2, tcol = (lane & 3) * 2;
    const bool hasBias = (bias != nullptr);
#pragma unroll
    for (int mf = 0; mf < 2; mf++) {
        int r0 = m0 + mbase + mf * 16 + trow;
#pragma unroll
        for (int ni = 0; ni < 8; ni++) {
            int c0 = n0 + nbase + ni * 8 + tcol;
#pragma unroll
            for (int cc = 0; cc < 2; cc++) {
                int c = c0 + cc;
                if (c < N) {
                    if (Ch) {
                        Ch[(size_t)r0 * ldc + c]       = __float2half(acc[mf][ni][cc]);
                        Ch[(size_t)(r0 + 8) * ldc + c] = __float2half(acc[mf][ni][2 + cc]);
                    } else {
                        float bv = hasBias ? bias[c] : 0.f;
                        float* Cp = C + (size_t)z * (size_t)M * (size_t)ldc;
                        Cp[(size_t)r0 * ldc + c]       = acc[mf][ni][cc] + bv;
                        Cp[(size_t)(r0 + 8) * ldc + c] = acc[mf][ni][2 + cc] + bv;
                    }
                }
            }
        }
    }
}

// ------- inputs: fp32 -> bf16 hi/lo + fp16 copy -------
__global__ void split_inputs_kernel(const float* __restrict__ src)
{
    int idx = blockIdx.x * 256 + threadIdx.x;
    if (idx >= BB * TT * DIN) return;
    int r = idx >> 9, c = idx & 511;
    float f = src[idx];
    __nv_bfloat16 hi = __float2bfloat16(f);
    g_inputs2[(size_t)r * 1024 + c]       = hi;
    g_inputs2[(size_t)r * 1024 + 512 + c] = __float2bfloat16(f - __bfloat162float(hi));
    g_inputsH[idx] = __float2half(f);
}

__global__ void split_kernel(const float* __restrict__ src, __nv_bfloat16* __restrict__ dst,
                             int total, int cols)
{
    int idx = blockIdx.x * 256 + threadIdx.x;
    if (idx >= total) return;
    int r = idx / cols, c = idx - r * cols;
    float f = src[idx];
    __nv_bfloat16 hi = __float2bfloat16(f);
    float lo = f - __bfloat162float(hi);
    size_t base = (size_t)r * 2 * cols + c;
    dst[base] = hi;
    dst[base + cols] = __float2bfloat16(lo);
}

__global__ void pack_kernel(const float* __restrict__ w_ih, const float* __restrict__ w_hh,
                            const float* __restrict__ b_ih, const float* __restrict__ b_hh,
                            const float* __restrict__ h2h_w)
{
    int idx = blockIdx.x * 256 + threadIdx.x;
    int n = idx >> 10, k = idx & 1023;
    float f = (k < 512) ? w_ih[(size_t)n * XW + k] : w_hh[n * 512 + (k - 512)];
    __nv_bfloat16 hi = __float2bfloat16(f);
    float lo = f - __bfloat162float(hi);
    g_wcat2[(size_t)n * 2048 + k]        = hi;
    g_wcat2[(size_t)n * 2048 + 1024 + k] = __float2bfloat16(lo);
    if (idx < G4) g_bias4[idx] = b_ih[idx] + b_hh[idx];
    if (idx < HH * HH) {
        int r = idx >> 9, c = idx & 511;
        float g = h2h_w[idx];
        __nv_bfloat16 ghi = __float2bfloat16(g);
        g_h2h2[(size_t)r * 1024 + c]       = ghi;
        g_h2h2[(size_t)r * 1024 + 512 + c] = __float2bfloat16(g - __bfloat162float(ghi));
    }
}

__global__ void init_kernel()
{
    int idx = blockIdx.x * 256 + threadIdx.x;
    int b = idx >> 9, hh = idx & 511;
    g_c[idx] = 0.f;
    __nv_bfloat16 z = __float2bfloat16(0.f);
    g_c2[(size_t)b * 1024 + hh]        = z;
    g_c2[(size_t)b * 1024 + 512 + hh]  = z;
    g_xcat2[(size_t)b * 2048 + 512 + hh]  = z;
    g_xcat2[(size_t)b * 2048 + 1536 + hh] = z;
}

// ---------------- fused attention (fp16 Hproj + fp16 inputs) ----------------
__global__ __launch_bounds__(256) void attention_kernel(
    const float* __restrict__ h2h_b, const float* __restrict__ score_w)
{
    const int b = blockIdx.x;
    const int tid = threadIdx.x;
    __shared__ __align__(16) float s_s[512];
    __shared__ __align__(16) float s_sc[512];
    __shared__ float s_e[96];

    for (int h = tid; h < 512; h += 256) {
        float v = h2h_b[h];
#pragma unroll
        for (int zz = 0; zz < 8; zz++)
            v += g_sparts[(size_t)zz * (BB * HH) + (size_t)b * HH + h];
        s_s[h] = v;
        s_sc[h] = score_w[h];
    }
    __syncthreads();

    const int w = tid >> 5, l = tid & 31;
    float svr[16], scr[16];
#pragma unroll
    for (int j = 0; j < 2; j++) {
        int fi = (j * 32 + l) * 2;
        *(float4*)&svr[j * 8]     = ((const float4*)s_s)[fi];
        *(float4*)&svr[j * 8 + 4] = ((const float4*)s_s)[fi + 1];
        *(float4*)&scr[j * 8]     = ((const float4*)s_sc)[fi];
        *(float4*)&scr[j * 8 + 4] = ((const float4*)s_sc)[fi + 1];
    }
    for (int t = w; t < TT; t += 8) {
        const float4* hrow = (const float4*)(g_HprojH + ((size_t)b * TT + t) * HH);
        float acc = 0.f;
#pragma unroll
        for (int j = 0; j < 2; j++) {
            float4 q = hrow[j * 32 + l];
            const __half2* hp2 = (const __half2*)&q;
#pragma unroll
            for (int p = 0; p < 4; p++) {
                float2 hv = __half22float2(hp2[p]);
                acc += scr[j * 8 + p * 2]     * tanhfast(hv.x + svr[j * 8 + p * 2]);
                acc += scr[j * 8 + p * 2 + 1] * tanhfast(hv.y + svr[j * 8 + p * 2 + 1]);
            }
        }
#pragma unroll
        for (int o = 16; o; o >>= 1) acc += __shfl_xor_sync(0xFFFFFFFFu, acc, o);
        if (l == 0) s_e[t] = acc;
    }
    __syncthreads();

    if (tid < 32) {
        float e0 = s_e[tid];
        float e1 = s_e[tid + 32];
        float e2 = (tid < 16) ? s_e[tid + 64] : -3.4e38f;
        float m = fmaxf(fmaxf(e0, e1), e2);
#pragma unroll
        for (int o = 16; o; o >>= 1) m = fmaxf(m, __shfl_xor_sync(0xFFFFFFFFu, m, o));
        float x0 = __expf(e0 - m), x1 = __expf(e1 - m);
        float x2 = (tid < 16) ? __expf(e2 - m) : 0.f;
        float sum = x0 + x1 + x2;
#pragma unroll
        for (int o = 16; o; o >>= 1) sum += __shfl_xor_sync(0xFFFFFFFFu, sum, o);
        float inv = 1.f / sum;
        s_e[tid] = x0 * inv; s_e[tid + 32] = x1 * inv;
        if (tid < 16) s_e[tid + 64] = x2 * inv;
    }
    __syncthreads();

    {
        float2 acc = make_float2(0.f, 0.f);
        const __half2* inp2 = (const __half2*)(g_inputsH + (size_t)b * TT * DIN);
        for (int t = 0; t < TT; t++) {
            float a = s_e[t];
            float2 v = __half22float2(inp2[t * 256 + tid]);
            acc.x += a * v.x; acc.y += a * v.y;
        }
        int d = 2 * tid;
        __nv_bfloat16 hx = __float2bfloat16(acc.x);
        __nv_bfloat16 hy = __float2bfloat16(acc.y);
        g_xcat2[(size_t)b * 2048 + d]            = hx;
        g_xcat2[(size_t)b * 2048 + d + 1]        = hy;
        g_xcat2[(size_t)b * 2048 + 1024 + d]     = __float2bfloat16(acc.x - __bfloat162float(hx));
        g_xcat2[(size_t)b * 2048 + 1024 + d + 1] = __float2bfloat16(acc.y - __bfloat162float(hy));
    }
}

// ---------------- LSTM pointwise ----------------
__global__ void lstm_pointwise(const float* __restrict__ w_ih, const int* __restrict__ targets,
                               int t)
{
    int idx = blockIdx.x * 256 + threadIdx.x;
    int b = idx >> 9, hh = idx & 511;
    int cls = targets[b * SS + t];
    const float* colp = w_ih + 512 + cls;

    float g4[4];
#pragma unroll
    for (int q = 0; q < 4; q++) {
        int gi = q * 512 + hh;
        float v = g_bias4[gi] + colp[(size_t)gi * XW];
#pragma unroll
        for (int zz = 0; zz < 2; zz++)
            v += g_gparts[(size_t)zz * (BB * G4) + (size_t)b * G4 + gi];
        g4[q] = v;
    }
    float ci = g_c[idx];
    float ig = sigf(g4[0]);
    float fg = sigf(g4[1]);
    float gg = tanhfast(g4[2]);
    float og = sigf(g4[3]);
    float cn = fg * ci + ig * gg;
    float hn = og * tanhfast(cn);
    g_c[idx] = cn;

    __nv_bfloat16 chi = __float2bfloat16(cn);
    g_c2[(size_t)b * 1024 + hh]       = chi;
    g_c2[(size_t)b * 1024 + 512 + hh] = __float2bfloat16(cn - __bfloat162float(chi));

    __nv_bfloat16 hhi = __float2bfloat16(hn);
    __nv_bfloat16 hlo = __float2bfloat16(hn - __bfloat162float(hhi));
    g_xcat2[(size_t)b * 2048 + 512 + hh]  = hhi;
    g_xcat2[(size_t)b * 2048 + 1536 + hh] = hlo;

    size_t hr = (size_t)b * SS + t;
    g_hs2[hr * 1024 + hh]       = hhi;
    g_hs2[hr * 1024 + 512 + hh] = hlo;
}

// ---------------- host launcher ----------------
extern "C" void kernel_launch(void* const* d_in, const int* in_sizes, int n_in,
                              void* d_out, int out_size)
{
    const float* inputs  = (const float*)d_in[0];
    const int*   targets = (const int*)  d_in[1];
    const float* i2h_w   = (const float*)d_in[2];
    const float* h2h_w   = (const float*)d_in[3];
    const float* h2h_b   = (const float*)d_in[4];
    const float* score_w = (const float*)d_in[5];
    const float* w_ih    = (const float*)d_in[6];
    const float* w_hh    = (const float*)d_in[7];
    const float* b_ih    = (const float*)d_in[8];
    const float* b_hh    = (const float*)d_in[9];
    const float* gen_w   = (const float*)d_in[10];
    const float* gen_b   = (const float*)d_in[11];
    float* out = (float*)d_out;

    static float *sparts = nullptr, *gparts;
    static __half *HprojH;
    static __nv_bfloat16 *inputs2, *i2h2, *genw2, *h2h2, *wcat2, *xcat2, *c2, *hs2;
    if (!sparts) {
        cudaGetSymbolAddress((void**)&sparts,  g_sparts);
        cudaGetSymbolAddress((void**)&gparts,  g_gparts);
        cudaGetSymbolAddress((void**)&HprojH,  g_HprojH);
        cudaGetSymbolAddress((void**)&inputs2, g_inputs2);
        cudaGetSymbolAddress((void**)&i2h2,    g_i2h2);
        cudaGetSymbolAddress((void**)&genw2,   g_genw2);
        cudaGetSymbolAddress((void**)&h2h2,    g_h2h2);
        cudaGetSymbolAddress((void**)&wcat2,   g_wcat2);
        cudaGetSymbolAddress((void**)&xcat2,   g_xcat2);
        cudaGetSymbolAddress((void**)&c2,      g_c2);
        cudaGetSymbolAddress((void**)&hs2,     g_hs2);
    }

    // ncu captured-launch idx 5 == our idx 3: keep Hproj MMA there.
    split_inputs_kernel<<<(BB * TT * DIN + 255) / 256, 256>>>(inputs);          // 0
    split_kernel<<<(HH * DIN + 255) / 256, 256>>>(i2h_w, i2h2, HH * DIN, DIN);  // 1
    init_kernel<<<(BB * HH) / 256, 256>>>();                                    // 2
    // 3: Hproj (fp16 out) = inputs @ i2h_w^T   <-- ncu capture target
    mma_bf16x3_nt<<<dim3(HH / 128, (BB * TT) / 128, 1), 256>>>(
        inputs2, i2h2, nullptr, nullptr, HprojH, BB * TT, HH, 512, 512, HH);
    pack_kernel<<<(G4 * 1024) / 256, 256>>>(w_ih, w_hh, b_ih, b_hh, h2h_w);     // 4
    split_kernel<<<(NC * HH + 255) / 256, 256>>>(gen_w, genw2, NC * HH, HH);    // 5

    for (int t = 0; t < SS; t++) {
        // sparts = c @ h2h_w^T   (split-K: 8 chunks of 64 hi-cols -> 128 blocks)
        mma_bf16x3_nt<<<dim3(HH / 128, BB / 128, 8), 256>>>(
            c2, h2h2, nullptr, sparts, nullptr, BB, HH, 512, 64, HH);

        attention_kernel<<<BB, 256>>>(h2h_b, score_w);

        // gparts = xcat @ wcat^T  (split-K: 2 chunks of 512 hi-cols)
        mma_bf16x3_nt<<<dim3(G4 / 128, BB / 128, 2), 256>>>(
            xcat2, wcat2, nullptr, gparts, nullptr, BB, G4, 1024, 512, G4);

        lstm_pointwise<<<(BB * HH) / 256, 256>>>(w_ih, targets, t);
    }

    // probs = hs @ gen_w^T + gen_b
    mma_bf16x3_nt<<<dim3((NC + 127) / 128, (BB * SS) / 128, 1), 256>>>(
        hs2, genw2, gen_b, out, nullptr, BB * SS, NC, 512, 512, NC);
}

// round 17
// speedup vs baseline: 1.2573x; 1.0464x over previous
#include <cuda_runtime.h>
#include <cuda_bf16.h>
#include <cuda_fp16.h>
#include <math.h>

typedef unsigned int u32;

// Problem dims (fixed by the reference)
#define BB   512
#define TT   80
#define DIN  512
#define HH   512
#define G4   2048      // 4*HH
#define NC   6625
#define SS   25
#define XW   7137      // DIN + NC  (w_ih row width)

// ---------------- scratch (device globals; no allocation allowed) ----------------
__device__ float g_bias4[G4];
__device__ float g_c[(size_t)BB * HH];              // cell state (exact fp32)
__device__ float g_gparts[2 * (size_t)BB * G4];     // split-K partials, gates GEMM
__device__ float g_sparts[8 * (size_t)BB * HH];     // split-K partials, s GEMM

// fp16 attention-path buffers
__device__ __half g_HprojH[(size_t)BB * TT * HH];   // 42 MB
__device__ __half g_inputsH[(size_t)BB * TT * DIN]; // 42 MB

// bf16 hi/lo GEMM operands
__device__ __nv_bfloat16 g_inputs2[(size_t)BB * TT * 1024]; // hi|lo, KH=512
__device__ __nv_bfloat16 g_i2h2[(size_t)HH * 1024];
__device__ __nv_bfloat16 g_genw2[(size_t)NC * 1024];
__device__ __nv_bfloat16 g_h2h2[(size_t)HH * 1024];
__device__ __nv_bfloat16 g_wcat2[(size_t)G4 * 2048];        // KH=1024
__device__ __nv_bfloat16 g_xcat2[(size_t)BB * 2048];        // KH=1024
__device__ __nv_bfloat16 g_c2[(size_t)BB * 1024];
__device__ __nv_bfloat16 g_hs2[(size_t)BB * SS * 1024];

__device__ __forceinline__ float sigf(float x) { return 1.f / (1.f + __expf(-x)); }
__device__ __forceinline__ float tanhfast(float x) {
    float e = __expf(2.f * x);
    return 1.f - 2.f / (e + 1.f);
}
__device__ __forceinline__ void cpasync16(u32 dst, const void* src) {
    asm volatile("cp.async.cg.shared.global [%0], [%1], 16;" :: "r"(dst), "l"(src));
}

// =================== bf16x3 tensor-core GEMM: C = A@B^T (+bias) ===================
// A2: [M][2*KHtot] bf16 (hi | lo). B2: [N][2*KHtot] same.
// blockIdx.z = split-K chunk over hi-k [z*kLenH, (z+1)*kLenH); 3 passes per chunk.
// K=64 stages (four K16 mma sub-steps per barrier), 3-stage cp.async pipeline,
// 96KB dynamic smem. Row = 64 bf16 = 128B = 8 chunks of 16B; chunk c stored at
// (c ^ (row&7)) — SW128-style, conflict-free for stores and ldmatrix.
// gridDim.z>1 -> raw float partials at C + z*M*ldc (bias null).
// If Ch != null: write fp16 to Ch (z must be 1).
#define MMA_SMEM (3 * 16384 * 2)    // 98304 B

__global__ __launch_bounds__(256) void mma_bf16x3_nt(
    const __nv_bfloat16* __restrict__ A2, const __nv_bfloat16* __restrict__ B2,
    const float* __restrict__ bias, float* __restrict__ C,
    __half* __restrict__ Ch,
    int M, int N, int KHtot, int kLenH, int ldc)
{
    const int npp   = kLenH >> 6;        // K64 iters per pass
    const int ITERS = 3 * npp;
    const int z      = blockIdx.z;
    const int kStart = z * kLenH;
    const int rowK2  = 2 * KHtot;

    extern __shared__ __align__(128) __nv_bfloat16 smemRaw[];
    const u32 asBase = (u32)__cvta_generic_to_shared(smemRaw);            // 3 x 16KB A
    const u32 bsBase = asBase + 3 * 16384;                                // 3 x 16KB B

    const int n0 = blockIdx.x * 128;
    const int m0 = blockIdx.y * 128;
    const int tid  = threadIdx.x;

    // ---- load geometry: thread -> row (tid>>1), chunk quad h = tid&1 ----
    const int row = tid >> 1, h = tid & 1;
    const bool bval = (n0 + row) < N;
    const __nv_bfloat16* aSrcRow = A2 + (size_t)(m0 + row) * rowK2;
    const __nv_bfloat16* bSrcRow = B2 + (size_t)(n0 + row) * rowK2;
    const int swzr = row & 7;
    u32 dOffs[4];
#pragma unroll
    for (int j = 0; j < 4; j++)
        dOffs[j] = row * 128 + (((h * 4 + j) ^ swzr) * 16);
    const u32 zero32 = 0;

    auto loadTiles = [&](int stg, int it) {
        int p = 0, kk = it;
        if (kk >= npp) { p++; kk -= npp; }
        if (kk >= npp) { p++; kk -= npp; }
        kk <<= 6;
        int acol = kStart + kk + ((p == 2) ? KHtot : 0) + h * 32;
        int bcol = kStart + kk + ((p == 1) ? KHtot : 0) + h * 32;
        u32 ab = asBase + stg * 16384;
        u32 bb = bsBase + stg * 16384;
#pragma unroll
        for (int j = 0; j < 4; j++)
            cpasync16(ab + dOffs[j], aSrcRow + acol + j * 8);
        if (bval) {
#pragma unroll
            for (int j = 0; j < 4; j++)
                cpasync16(bb + dOffs[j], bSrcRow + bcol + j * 8);
        } else {
#pragma unroll
            for (int j = 0; j < 4; j++)
                asm volatile("st.shared.v4.b32 [%0], {%1,%1,%1,%1};"
                             :: "r"(bb + dOffs[j]), "r"(zero32));
        }
        asm volatile("cp.async.commit_group;");
    };

    // ---- fragment addressing ----
    const int warp = tid >> 5, lane = tid & 31;
    const int wm = warp >> 1, wn = warp & 1;
    const int mbase = wm * 32, nbase = wn * 64;

    u32 aRowTerm[2]; int aSwz[2];
    const int kcA = lane >> 4;
#pragma unroll
    for (int mf = 0; mf < 2; mf++) {
        int rA = mbase + mf * 16 + (lane & 15);
        aRowTerm[mf] = rA * 128;
        aSwz[mf] = rA & 7;
    }
    const int sel = lane >> 3, lb = lane & 7;
    const int kcB = sel & 1;
    u32 bRowTerm[4]; int bSwz[4];
#pragma unroll
    for (int nn = 0; nn < 4; nn++) {
        int rB = nbase + nn * 16 + ((sel >> 1) & 1) * 8 + lb;
        bRowTerm[nn] = rB * 128;
        bSwz[nn] = rB & 7;
    }

    float acc[2][8][4];
#pragma unroll
    for (int i = 0; i < 2; i++)
#pragma unroll
        for (int j = 0; j < 8; j++)
#pragma unroll
            for (int q = 0; q < 4; q++) acc[i][j][q] = 0.f;

    loadTiles(0, 0);
    if (ITERS > 1) loadTiles(1, 1);

    for (int it = 0; it < ITERS; ++it) {
        if (it + 1 < ITERS) asm volatile("cp.async.wait_group 1;");
        else                asm volatile("cp.async.wait_group 0;");
        __syncthreads();

        int nx = it + 2;
        if (nx < ITERS) loadTiles(nx % 3, nx);

        const int stg = it % 3;
        const u32 aB = asBase + stg * 16384;
        const u32 bB = bsBase + stg * 16384;

#pragma unroll
        for (int ks = 0; ks < 4; ks++) {
            u32 fa[2][4];
#pragma unroll
            for (int mf = 0; mf < 2; mf++) {
                u32 addr = aB + aRowTerm[mf] + (((ks * 2 + kcA) ^ aSwz[mf]) * 16);
                asm volatile("ldmatrix.sync.aligned.m8n8.x4.shared.b16 {%0,%1,%2,%3}, [%4];"
                             : "=r"(fa[mf][0]), "=r"(fa[mf][1]), "=r"(fa[mf][2]), "=r"(fa[mf][3])
                             : "r"(addr));
            }
            u32 fb[8][2];
#pragma unroll
            for (int nn = 0; nn < 4; nn++) {
                u32 addr = bB + bRowTerm[nn] + (((ks * 2 + kcB) ^ bSwz[nn]) * 16);
                asm volatile("ldmatrix.sync.aligned.m8n8.x4.shared.b16 {%0,%1,%2,%3}, [%4];"
                             : "=r"(fb[2*nn][0]), "=r"(fb[2*nn][1]),
                               "=r"(fb[2*nn+1][0]), "=r"(fb[2*nn+1][1])
                             : "r"(addr));
            }
#pragma unroll
            for (int mf = 0; mf < 2; mf++)
#pragma unroll
                for (int ni = 0; ni < 8; ni++) {
                    asm volatile(
                        "mma.sync.aligned.m16n8k16.row.col.f32.bf16.bf16.f32 "
                        "{%0,%1,%2,%3}, {%4,%5,%6,%7}, {%8,%9}, {%0,%1,%2,%3};"
                        : "+f"(acc[mf][ni][0]), "+f"(acc[mf][ni][1]),
                          "+f"(acc[mf][ni][2]), "+f"(acc[mf][ni][3])
                        : "r"(fa[mf][0]), "r"(fa[mf][1]), "r"(fa[mf][2]), "r"(fa[mf][3]),
                          "r"(fb[ni][0]), "r"(fb[ni][1]));
                }
        }
    }

    // epilogue
    const int trow = lane >> 2, tcol = (lane & 3) * 2;
    const bool hasBias = (bias != nullptr);
#pragma unroll
    for (int mf = 0; mf < 2; mf++) {
        int r0 = m0 + mbase + mf * 16 + trow;
#pragma unroll
        for (int ni = 0; ni < 8; ni++) {
            int c0 = n0 + nbase + ni * 8 + tcol;
#pragma unroll
            for (int cc = 0; cc < 2; cc++) {
                int c = c0 + cc;
                if (c < N) {
                    if (Ch) {
                        Ch[(size_t)r0 * ldc + c]       = __float2half(acc[mf][ni][cc]);
                        Ch[(size_t)(r0 + 8) * ldc + c] = __float2half(acc[mf][ni][2 + cc]);
                    } else {
                        float bv = hasBias ? bias[c] : 0.f;
                        float* Cp = C + (size_t)z * (size_t)M * (size_t)ldc;
                        Cp[(size_t)r0 * ldc + c]       = acc[mf][ni][cc] + bv;
                        Cp[(size_t)(r0 + 8) * ldc + c] = acc[mf][ni][2 + cc] + bv;
                    }
                }
            }
        }
    }
}

// ------- inputs: fp32 -> bf16 hi/lo + fp16 copy -------
__global__ void split_inputs_kernel(const float* __restrict__ src)
{
    int idx = blockIdx.x * 256 + threadIdx.x;
    if (idx >= BB * TT * DIN) return;
    int r = idx >> 9, c = idx & 511;
    float f = src[idx];
    __nv_bfloat16 hi = __float2bfloat16(f);
    g_inputs2[(size_t)r * 1024 + c]       = hi;
    g_inputs2[(size_t)r * 1024 + 512 + c] = __float2bfloat16(f - __bfloat162float(hi));
    g_inputsH[idx] = __float2half(f);
}

__global__ void split_kernel(const float* __restrict__ src, __nv_bfloat16* __restrict__ dst,
                             int total, int cols)
{
    int idx = blockIdx.x * 256 + threadIdx.x;
    if (idx >= total) return;
    int r = idx / cols, c = idx - r * cols;
    float f = src[idx];
    __nv_bfloat16 hi = __float2bfloat16(f);
    float lo = f - __bfloat162float(hi);
    size_t base = (size_t)r * 2 * cols + c;
    dst[base] = hi;
    dst[base + cols] = __float2bfloat16(lo);
}

__global__ void pack_kernel(const float* __restrict__ w_ih, const float* __restrict__ w_hh,
                            const float* __restrict__ b_ih, const float* __restrict__ b_hh,
                            const float* __restrict__ h2h_w)
{
    int idx = blockIdx.x * 256 + threadIdx.x;
    int n = idx >> 10, k = idx & 1023;
    float f = (k < 512) ? w_ih[(size_t)n * XW + k] : w_hh[n * 512 + (k - 512)];
    __nv_bfloat16 hi = __float2bfloat16(f);
    float lo = f - __bfloat162float(hi);
    g_wcat2[(size_t)n * 2048 + k]        = hi;
    g_wcat2[(size_t)n * 2048 + 1024 + k] = __float2bfloat16(lo);
    if (idx < G4) g_bias4[idx] = b_ih[idx] + b_hh[idx];
    if (idx < HH * HH) {
        int r = idx >> 9, c = idx & 511;
        float g = h2h_w[idx];
        __nv_bfloat16 ghi = __float2bfloat16(g);
        g_h2h2[(size_t)r * 1024 + c]       = ghi;
        g_h2h2[(size_t)r * 1024 + 512 + c] = __float2bfloat16(g - __bfloat162float(ghi));
    }
}

__global__ void init_kernel()
{
    int idx = blockIdx.x * 256 + threadIdx.x;
    int b = idx >> 9, hh = idx & 511;
    g_c[idx] = 0.f;
    __nv_bfloat16 z = __float2bfloat16(0.f);
    g_c2[(size_t)b * 1024 + hh]        = z;
    g_c2[(size_t)b * 1024 + 512 + hh]  = z;
    g_xcat2[(size_t)b * 2048 + 512 + hh]  = z;
    g_xcat2[(size_t)b * 2048 + 1536 + hh] = z;
}

// ---------------- fused attention (fp16 Hproj + fp16 inputs) ----------------
__global__ __launch_bounds__(256) void attention_kernel(
    const float* __restrict__ h2h_b, const float* __restrict__ score_w)
{
    const int b = blockIdx.x;
    const int tid = threadIdx.x;
    __shared__ __align__(16) float s_s[512];
    __shared__ __align__(16) float s_sc[512];
    __shared__ float s_e[96];

    for (int h = tid; h < 512; h += 256) {
        float v = h2h_b[h];
#pragma unroll
        for (int zz = 0; zz < 8; zz++)
            v += g_sparts[(size_t)zz * (BB * HH) + (size_t)b * HH + h];
        s_s[h] = v;
        s_sc[h] = score_w[h];
    }
    __syncthreads();

    const int w = tid >> 5, l = tid & 31;
    float svr[16], scr[16];
#pragma unroll
    for (int j = 0; j < 2; j++) {
        int fi = (j * 32 + l) * 2;
        *(float4*)&svr[j * 8]     = ((const float4*)s_s)[fi];
        *(float4*)&svr[j * 8 + 4] = ((const float4*)s_s)[fi + 1];
        *(float4*)&scr[j * 8]     = ((const float4*)s_sc)[fi];
        *(float4*)&scr[j * 8 + 4] = ((const float4*)s_sc)[fi + 1];
    }
    for (int t = w; t < TT; t += 8) {
        const float4* hrow = (const float4*)(g_HprojH + ((size_t)b * TT + t) * HH);
        float acc = 0.f;
#pragma unroll
        for (int j = 0; j < 2; j++) {
            float4 q = hrow[j * 32 + l];
            const __half2* hp2 = (const __half2*)&q;
#pragma unroll
            for (int p = 0; p < 4; p++) {
                float2 hv = __half22float2(hp2[p]);
                acc += scr[j * 8 + p * 2]     * tanhfast(hv.x + svr[j * 8 + p * 2]);
                acc += scr[j * 8 + p * 2 + 1] * tanhfast(hv.y + svr[j * 8 + p * 2 + 1]);
            }
        }
#pragma unroll
        for (int o = 16; o; o >>= 1) acc += __shfl_xor_sync(0xFFFFFFFFu, acc, o);
        if (l == 0) s_e[t] = acc;
    }
    __syncthreads();

    if (tid < 32) {
        float e0 = s_e[tid];
        float e1 = s_e[tid + 32];
        float e2 = (tid < 16) ? s_e[tid + 64] : -3.4e38f;
        float m = fmaxf(fmaxf(e0, e1), e2);
#pragma unroll
        for (int o = 16; o; o >>= 1) m = fmaxf(m, __shfl_xor_sync(0xFFFFFFFFu, m, o));
        float x0 = __expf(e0 - m), x1 = __expf(e1 - m);
        float x2 = (tid < 16) ? __expf(e2 - m) : 0.f;
        float sum = x0 + x1 + x2;
#pragma unroll
        for (int o = 16; o; o >>= 1) sum += __shfl_xor_sync(0xFFFFFFFFu, sum, o);
        float inv = 1.f / sum;
        s_e[tid] = x0 * inv; s_e[tid + 32] = x1 * inv;
        if (tid < 16) s_e[tid + 64] = x2 * inv;
    }
    __syncthreads();

    {
        float2 acc = make_float2(0.f, 0.f);
        const __half2* inp2 = (const __half2*)(g_inputsH + (size_t)b * TT * DIN);
        for (int t = 0; t < TT; t++) {
            float a = s_e[t];
            float2 v = __half22float2(inp2[t * 256 + tid]);
            acc.x += a * v.x; acc.y += a * v.y;
        }
        int d = 2 * tid;
        __nv_bfloat16 hx = __float2bfloat16(acc.x);
        __nv_bfloat16 hy = __float2bfloat16(acc.y);
        g_xcat2[(size_t)b * 2048 + d]            = hx;
        g_xcat2[(size_t)b * 2048 + d + 1]        = hy;
        g_xcat2[(size_t)b * 2048 + 1024 + d]     = __float2bfloat16(acc.x - __bfloat162float(hx));
        g_xcat2[(size_t)b * 2048 + 1024 + d + 1] = __float2bfloat16(acc.y - __bfloat162float(hy));
    }
}

// ---------------- LSTM pointwise ----------------
__global__ void lstm_pointwise(const float* __restrict__ w_ih, const int* __restrict__ targets,
                               int t)
{
    int idx = blockIdx.x * 256 + threadIdx.x;
    int b = idx >> 9, hh = idx & 511;
    int cls = targets[b * SS + t];
    const float* colp = w_ih + 512 + cls;

    float g4[4];
#pragma unroll
    for (int q = 0; q < 4; q++) {
        int gi = q * 512 + hh;
        float v = g_bias4[gi] + colp[(size_t)gi * XW];
#pragma unroll
        for (int zz = 0; zz < 2; zz++)
            v += g_gparts[(size_t)zz * (BB * G4) + (size_t)b * G4 + gi];
        g4[q] = v;
    }
    float ci = g_c[idx];
    float ig = sigf(g4[0]);
    float fg = sigf(g4[1]);
    float gg = tanhfast(g4[2]);
    float og = sigf(g4[3]);
    float cn = fg * ci + ig * gg;
    float hn = og * tanhfast(cn);
    g_c[idx] = cn;

    __nv_bfloat16 chi = __float2bfloat16(cn);
    g_c2[(size_t)b * 1024 + hh]       = chi;
    g_c2[(size_t)b * 1024 + 512 + hh] = __float2bfloat16(cn - __bfloat162float(chi));

    __nv_bfloat16 hhi = __float2bfloat16(hn);
    __nv_bfloat16 hlo = __float2bfloat16(hn - __bfloat162float(hhi));
    g_xcat2[(size_t)b * 2048 + 512 + hh]  = hhi;
    g_xcat2[(size_t)b * 2048 + 1536 + hh] = hlo;

    size_t hr = (size_t)b * SS + t;
    g_hs2[hr * 1024 + hh]       = hhi;
    g_hs2[hr * 1024 + 512 + hh] = hlo;
}

// ---------------- host launcher ----------------
extern "C" void kernel_launch(void* const* d_in, const int* in_sizes, int n_in,
                              void* d_out, int out_size)
{
    const float* inputs  = (const float*)d_in[0];
    const int*   targets = (const int*)  d_in[1];
    const float* i2h_w   = (const float*)d_in[2];
    const float* h2h_w   = (const float*)d_in[3];
    const float* h2h_b   = (const float*)d_in[4];
    const float* score_w = (const float*)d_in[5];
    const float* w_ih    = (const float*)d_in[6];
    const float* w_hh    = (const float*)d_in[7];
    const float* b_ih    = (const float*)d_in[8];
    const float* b_hh    = (const float*)d_in[9];
    const float* gen_w   = (const float*)d_in[10];
    const float* gen_b   = (const float*)d_in[11];
    float* out = (float*)d_out;

    static float *sparts = nullptr, *gparts;
    static __half *HprojH;
    static __nv_bfloat16 *inputs2, *i2h2, *genw2, *h2h2, *wcat2, *xcat2, *c2, *hs2;
    if (!sparts) {
        cudaGetSymbolAddress((void**)&sparts,  g_sparts);
        cudaGetSymbolAddress((void**)&gparts,  g_gparts);
        cudaGetSymbolAddress((void**)&HprojH,  g_HprojH);
        cudaGetSymbolAddress((void**)&inputs2, g_inputs2);
        cudaGetSymbolAddress((void**)&i2h2,    g_i2h2);
        cudaGetSymbolAddress((void**)&genw2,   g_genw2);
        cudaGetSymbolAddress((void**)&h2h2,    g_h2h2);
        cudaGetSymbolAddress((void**)&wcat2,   g_wcat2);
        cudaGetSymbolAddress((void**)&xcat2,   g_xcat2);
        cudaGetSymbolAddress((void**)&c2,      g_c2);
        cudaGetSymbolAddress((void**)&hs2,     g_hs2);
        cudaFuncSetAttribute(mma_bf16x3_nt,
                             cudaFuncAttributeMaxDynamicSharedMemorySize, MMA_SMEM);
    }

    // ncu captured-launch idx 5 == our idx 3: keep Hproj MMA there.
    split_inputs_kernel<<<(BB * TT * DIN + 255) / 256, 256>>>(inputs);          // 0
    split_kernel<<<(HH * DIN + 255) / 256, 256>>>(i2h_w, i2h2, HH * DIN, DIN);  // 1
    init_kernel<<<(BB * HH) / 256, 256>>>();                                    // 2
    // 3: Hproj (fp16 out) = inputs @ i2h_w^T   <-- ncu capture target
    mma_bf16x3_nt<<<dim3(HH / 128, (BB * TT) / 128, 1), 256, MMA_SMEM>>>(
        inputs2, i2h2, nullptr, nullptr, HprojH, BB * TT, HH, 512, 512, HH);
    pack_kernel<<<(G4 * 1024) / 256, 256>>>(w_ih, w_hh, b_ih, b_hh, h2h_w);     // 4
    split_kernel<<<(NC * HH + 255) / 256, 256>>>(gen_w, genw2, NC * HH, HH);    // 5

    for (int t = 0; t < SS; t++) {
        // sparts = c @ h2h_w^T   (split-K: 8 chunks of 64 hi-cols -> 128 blocks)
        mma_bf16x3_nt<<<dim3(HH / 128, BB / 128, 8), 256, MMA_SMEM>>>(
            c2, h2h2, nullptr, sparts, nullptr, BB, HH, 512, 64, HH);

        attention_kernel<<<BB, 256>>>(h2h_b, score_w);

        // gparts = xcat @ wcat^T  (split-K: 2 chunks of 512 hi-cols)
        mma_bf16x3_nt<<<dim3(G4 / 128, BB / 128, 2), 256, MMA_SMEM>>>(
            xcat2, wcat2, nullptr, gparts, nullptr, BB, G4, 1024, 512, G4);

        lstm_pointwise<<<(BB * HH) / 256, 256>>>(w_ih, targets, t);
    }

    // probs = hs @ gen_w^T + gen_b
    mma_bf16x3_nt<<<dim3((NC + 127) / 128, (BB * SS) / 128, 1), 256, MMA_SMEM>>>(
        hs2, genw2, gen_b, out, nullptr, BB * SS, NC, 512, 512, NC);
}